// round 12
// baseline (speedup 1.0000x reference)
#include <cuda_runtime.h>
#include <stdint.h>
#include <math.h>

#define D        512
#define NCHUNK   16
#define BMAX     16
#define NEG_INF  -1e30f

// ---------------- scratch (no allocation allowed) ----------------
__device__ float g_q[BMAX * D];
__device__ float g_pm[BMAX * NCHUNK];
__device__ float g_ps[BMAX * NCHUNK];
__device__ float g_pctx[BMAX * NCHUNK * D];
__device__ int   g_cnt[BMAX * NCHUNK];             // unmasked rows per chunk
__device__ int   g_lidx[BMAX * NCHUNK * 512];      // local row idx within chunk
__device__ unsigned long long g_bar = 0;

// Replay-safe grid barrier (monotonic ticket counter).
__device__ __forceinline__ void grid_barrier()
{
    __syncthreads();
    if (threadIdx.x == 0) {
        __threadfence();
        const unsigned long long g = gridDim.x;
        unsigned long long t = atomicAdd(&g_bar, 1ULL);
        unsigned long long target = (t / g + 1ULL) * g;
        volatile unsigned long long* p = &g_bar;
        while (*p < target) __nanosleep(64);
        __threadfence();
    }
    __syncthreads();
}

__device__ __forceinline__ float dot4(const float4 a, const float4 b)
{
    float r;
    r = a.x * b.x;
    r = fmaf(a.y, b.y, r);
    r = fmaf(a.z, b.z, r);
    r = fmaf(a.w, b.w, r);
    return r;
}

// ---------------- fused kernel ----------------
// grid = B*NCHUNK = 256 blocks, block = 256 (8 warps), 2 blocks/SM.
__global__ void __launch_bounds__(256, 2) fused_attn(
    const float* __restrict__ query,
    const float* __restrict__ value,
    const int*   __restrict__ mask,
    const float* __restrict__ W_align,
    const float* __restrict__ b_align,
    const float* __restrict__ W_query,
    const float* __restrict__ b_query,
    const float* __restrict__ W_value,
    const float* __restrict__ b_value,
    float* __restrict__ out,
    int L)
{
    const int bid  = blockIdx.x;
    const int b    = bid >> 4;
    const int seg  = bid & 15;
    const int tid  = threadIdx.x;
    const int warp = tid >> 5;
    const int lane = tid & 31;

    __shared__ float s_vec[D];             // query row (ph1) / combined ctx (ph3)
    __shared__ float s_q[D];
    __shared__ int   s_idx[512];
    __shared__ int   s_pop[16], s_off[16];
    __shared__ int   s_pfx[17];
    __shared__ float sm_m[8], sm_s[8];
    __shared__ float sm_ctx[8][D];
    __shared__ float s_e[NCHUNK];
    __shared__ float s_Sinv;

    // ================= Phase 1: qproj + per-chunk mask compaction ==========
    for (int i = tid; i < D; i += 256) s_vec[i] = query[(size_t)b * D + i];
    __syncthreads();
    {
        const int d0 = seg * 32 + warp * 4;
        const float4* x4 = reinterpret_cast<const float4*>(s_vec);
        float4 x[4];
#pragma unroll
        for (int k = 0; k < 4; k++) x[k] = x4[lane + 32 * k];

        float acc[4] = {0.f, 0.f, 0.f, 0.f};
#pragma unroll
        for (int i = 0; i < 4; i++) {
            const float4* wrow = reinterpret_cast<const float4*>(W_align + (size_t)(d0 + i) * D);
#pragma unroll
            for (int k = 0; k < 4; k++) {
                float4 w = wrow[lane + 32 * k];
                acc[i] = fmaf(w.x, x[k].x, acc[i]); acc[i] = fmaf(w.y, x[k].y, acc[i]);
                acc[i] = fmaf(w.z, x[k].z, acc[i]); acc[i] = fmaf(w.w, x[k].w, acc[i]);
            }
        }
#pragma unroll
        for (int o = 16; o > 0; o >>= 1) {
#pragma unroll
            for (int i = 0; i < 4; i++) acc[i] += __shfl_xor_sync(0xffffffffu, acc[i], o);
        }
        if (lane < 4)
            g_q[(size_t)b * D + d0 + lane] = acc[lane] + b_align[d0 + lane];
    }

    // ---- compact this chunk's unmasked rows into the global per-batch list ----
    {
        const int* mrow = mask + (size_t)b * L + seg * 512;
        unsigned a0 = __ballot_sync(0xffffffffu, mrow[tid]       == 0);
        unsigned a1 = __ballot_sync(0xffffffffu, mrow[tid + 256] == 0);
        if (lane == 0) { s_pop[warp] = __popc(a0); s_pop[warp + 8] = __popc(a1); }
        __syncthreads();
        if (tid == 0) {
            int acc = 0;
#pragma unroll
            for (int i = 0; i < 16; i++) { s_off[i] = acc; acc += s_pop[i]; }
            g_cnt[bid] = acc;
        }
        __syncthreads();
        int* dst = g_lidx + bid * 512;
        if ((a0 >> lane) & 1)
            dst[s_off[warp]     + __popc(a0 & ((1u << lane) - 1))] = warp * 32 + lane;
        if ((a1 >> lane) & 1)
            dst[s_off[warp + 8] + __popc(a1 & ((1u << lane) - 1))] = 256 + warp * 32 + lane;
    }

    grid_barrier();   // q + compacted lists visible

    // ================= Phase 2: online-softmax, globally balanced ==========
    {
        // prefix over the batch's 16 chunk counts (deterministic warp scan)
        if (warp == 0) {
            int v = (lane < 16) ? g_cnt[(b << 4) + lane] : 0;
#pragma unroll
            for (int o = 1; o < 16; o <<= 1) {
                int u = __shfl_up_sync(0xffffffffu, v, o);
                if (lane >= o) v += u;
            }
            if (lane < 16) s_pfx[lane + 1] = v;
            if (lane == 0) s_pfx[0] = 0;
        }
        __syncthreads();
        const int Tb  = s_pfx[16];
        const int lo  = (seg * Tb) >> 4;
        const int hi  = ((seg + 1) * Tb) >> 4;
        const int cnt = hi - lo;

        // materialize this block's balanced slice of row indices (batch-local)
        for (int t = tid; t < cnt; t += 256) {
            const int p = lo + t;
            int c = 0;
#pragma unroll
            for (int i = 1; i < 16; i++) if (s_pfx[i] <= p) c = i;
            s_idx[t] = (c << 9) + g_lidx[((b << 4) + c) * 512 + (p - s_pfx[c])];
        }
        __syncthreads();

        const float4* q4 = reinterpret_cast<const float4*>(g_q + b * D);
        float4 q[4];
#pragma unroll
        for (int k = 0; k < 4; k++) q[k] = q4[lane + 32 * k];

        float m = NEG_INF, s = 0.f;
        float4 ctx[4];
#pragma unroll
        for (int k = 0; k < 4; k++) ctx[k] = make_float4(0.f, 0.f, 0.f, 0.f);

        const float* vbase = value + (size_t)b * L * D;

        for (int t0 = warp * 4; t0 < cnt; t0 += 32) {
            const int n = min(4, cnt - t0);
            const int j0 = s_idx[t0];
            const int j1 = s_idx[t0 + (n > 1 ? 1 : 0)];
            const int j2 = s_idx[t0 + (n > 2 ? 2 : 0)];
            const int j3 = s_idx[t0 + (n > 3 ? 3 : 0)];

            const float4* p0 = reinterpret_cast<const float4*>(vbase + (size_t)j0 * D);
            const float4* p1 = reinterpret_cast<const float4*>(vbase + (size_t)j1 * D);
            const float4* p2 = reinterpret_cast<const float4*>(vbase + (size_t)j2 * D);
            const float4* p3 = reinterpret_cast<const float4*>(vbase + (size_t)j3 * D);

            float4 v0[4], v1[4], v2[4], v3[4];
#pragma unroll
            for (int k = 0; k < 4; k++) v0[k] = __ldcs(p0 + lane + 32 * k);
#pragma unroll
            for (int k = 0; k < 4; k++) v1[k] = __ldcs(p1 + lane + 32 * k);
#pragma unroll
            for (int k = 0; k < 4; k++) v2[k] = __ldcs(p2 + lane + 32 * k);
#pragma unroll
            for (int k = 0; k < 4; k++) v3[k] = __ldcs(p3 + lane + 32 * k);

            float s0 = 0.f, s1 = 0.f, s2 = 0.f, s3 = 0.f;
#pragma unroll
            for (int k = 0; k < 4; k++) {
                s0 += dot4(v0[k], q[k]);
                s1 += dot4(v1[k], q[k]);
                s2 += dot4(v2[k], q[k]);
                s3 += dot4(v3[k], q[k]);
            }
#pragma unroll
            for (int o = 16; o > 0; o >>= 1) {
                s0 += __shfl_xor_sync(0xffffffffu, s0, o);
                s1 += __shfl_xor_sync(0xffffffffu, s1, o);
                s2 += __shfl_xor_sync(0xffffffffu, s2, o);
                s3 += __shfl_xor_sync(0xffffffffu, s3, o);
            }
            if (n < 2) s1 = NEG_INF;
            if (n < 3) s2 = NEG_INF;
            if (n < 4) s3 = NEG_INF;

            const float m_new = fmaxf(fmaxf(m, fmaxf(s0, s1)), fmaxf(s2, s3));
            const float corr = __expf(m  - m_new);
            const float w0   = __expf(s0 - m_new);
            const float w1   = __expf(s1 - m_new);
            const float w2   = __expf(s2 - m_new);
            const float w3   = __expf(s3 - m_new);
            s = s * corr + w0 + w1 + w2 + w3;
#pragma unroll
            for (int k = 0; k < 4; k++) {
                ctx[k].x = ctx[k].x * corr + fmaf(w1, v1[k].x, w0 * v0[k].x)
                                           + fmaf(w3, v3[k].x, w2 * v2[k].x);
                ctx[k].y = ctx[k].y * corr + fmaf(w1, v1[k].y, w0 * v0[k].y)
                                           + fmaf(w3, v3[k].y, w2 * v2[k].y);
                ctx[k].z = ctx[k].z * corr + fmaf(w1, v1[k].z, w0 * v0[k].z)
                                           + fmaf(w3, v3[k].z, w2 * v2[k].z);
                ctx[k].w = ctx[k].w * corr + fmaf(w1, v1[k].w, w0 * v0[k].w)
                                           + fmaf(w3, v3[k].w, w2 * v2[k].w);
            }
            m = m_new;
        }

        // ---- merge the 8 warps' partials ----
        if (lane == 0) { sm_m[warp] = m; sm_s[warp] = s; }
#pragma unroll
        for (int k = 0; k < 4; k++) {
            const int i = (lane + 32 * k) * 4;
            sm_ctx[warp][i + 0] = ctx[k].x;
            sm_ctx[warp][i + 1] = ctx[k].y;
            sm_ctx[warp][i + 2] = ctx[k].z;
            sm_ctx[warp][i + 3] = ctx[k].w;
        }
        __syncthreads();

        float M = NEG_INF;
#pragma unroll
        for (int wi = 0; wi < 8; wi++) M = fmaxf(M, sm_m[wi]);
        float e[8];
#pragma unroll
        for (int wi = 0; wi < 8; wi++) e[wi] = __expf(sm_m[wi] - M);

        float o0 = 0.f, o1 = 0.f;
#pragma unroll
        for (int wi = 0; wi < 8; wi++) {
            o0 = fmaf(sm_ctx[wi][tid],       e[wi], o0);
            o1 = fmaf(sm_ctx[wi][tid + 256], e[wi], o1);
        }
        const int pidx = bid;
        g_pctx[(size_t)pidx * D + tid]       = o0;
        g_pctx[(size_t)pidx * D + tid + 256] = o1;

        if (tid == 0) {
            float S = 0.f;
#pragma unroll
            for (int wi = 0; wi < 8; wi++) S = fmaf(sm_s[wi], e[wi], S);
            g_pm[pidx] = M;
            g_ps[pidx] = S;
        }
    }

    grid_barrier();

    // ================= Phase 3: combine + dual GEMV + tanh =================
    {
        if (warp == 0) {
            float mv = (lane < NCHUNK) ? g_pm[b * NCHUNK + lane] : NEG_INF;
            float M = mv;
#pragma unroll
            for (int o = 16; o > 0; o >>= 1) M = fmaxf(M, __shfl_xor_sync(0xffffffffu, M, o));
            float e  = (lane < NCHUNK) ? __expf(mv - M) : 0.f;
            float Sp = (lane < NCHUNK) ? g_ps[b * NCHUNK + lane] * e : 0.f;
#pragma unroll
            for (int o = 16; o > 0; o >>= 1) Sp += __shfl_xor_sync(0xffffffffu, Sp, o);
            if (lane < NCHUNK) s_e[lane] = e;
            if (lane == 0) s_Sinv = 1.f / Sp;
        }
        __syncthreads();

        const float Sinv = s_Sinv;
#pragma unroll
        for (int r = 0; r < 2; r++) {
            const int d = tid + 256 * r;
            const float* pc = g_pctx + (size_t)b * NCHUNK * D + d;
            float acc = 0.f;
#pragma unroll
            for (int c = 0; c < NCHUNK; c++)
                acc = fmaf(pc[(size_t)c * D], s_e[c], acc);
            s_vec[d] = acc * Sinv;
            s_q[d]   = g_q[(size_t)b * D + d];
        }
        __syncthreads();

        const int d0 = seg * 32 + warp * 4;
        const float4* c4 = reinterpret_cast<const float4*>(s_vec);
        const float4* q4 = reinterpret_cast<const float4*>(s_q);
        float4 cx[4], qx[4];
#pragma unroll
        for (int k = 0; k < 4; k++) { cx[k] = c4[lane + 32 * k]; qx[k] = q4[lane + 32 * k]; }

        float acc[4] = {0.f, 0.f, 0.f, 0.f};
#pragma unroll
        for (int i = 0; i < 4; i++) {
            const float4* wv = reinterpret_cast<const float4*>(W_value + (size_t)(d0 + i) * D);
            const float4* wq = reinterpret_cast<const float4*>(W_query + (size_t)(d0 + i) * D);
#pragma unroll
            for (int k = 0; k < 4; k++) {
                float4 a = wv[lane + 32 * k];
                float4 g = wq[lane + 32 * k];
                acc[i] += dot4(a, cx[k]);
                acc[i] += dot4(g, qx[k]);
            }
        }
#pragma unroll
        for (int o = 16; o > 0; o >>= 1) {
#pragma unroll
            for (int i = 0; i < 4; i++) acc[i] += __shfl_xor_sync(0xffffffffu, acc[i], o);
        }
        if (lane < 4) {
            const int d = d0 + lane;
            out[(size_t)b * D + d] = tanhf(acc[lane] + b_value[d] + b_query[d]);
        }
    }
}

// ---------------- launch ----------------
extern "C" void kernel_launch(void* const* d_in, const int* in_sizes, int n_in,
                              void* d_out, int out_size)
{
    const float* query   = (const float*)d_in[0];
    const float* value   = (const float*)d_in[1];
    const int*   mask    = (const int*)  d_in[2];
    const float* W_align = (const float*)d_in[3];
    const float* b_align = (const float*)d_in[4];
    const float* W_query = (const float*)d_in[5];
    const float* b_query = (const float*)d_in[6];
    const float* W_value = (const float*)d_in[7];
    const float* b_value = (const float*)d_in[8];
    float* out = (float*)d_out;

    const int B = in_sizes[0] / D;          // 16
    const int L = in_sizes[2] / B;          // 8192

    fused_attn<<<B * NCHUNK, 256>>>(query, value, mask,
                                    W_align, b_align, W_query, b_query,
                                    W_value, b_value, out, L);
}

// round 13
// speedup vs baseline: 1.0073x; 1.0073x over previous
#include <cuda_runtime.h>
#include <stdint.h>
#include <math.h>

#define D        512
#define NCHUNK   16
#define BMAX     16
#define NEG_INF  -1e30f

// ---------------- scratch (no allocation allowed) ----------------
__device__ float g_q[BMAX * D];
__device__ float g_pm[BMAX * NCHUNK];
__device__ float g_ps[BMAX * NCHUNK];
__device__ float g_pctx[BMAX * NCHUNK * D];
__device__ unsigned long long g_barb[BMAX];        // per-batch ticket counters

// Replay-safe per-batch barrier (16 arrivals per generation, monotonic).
__device__ __forceinline__ void batch_barrier(int b)
{
    __syncthreads();
    if (threadIdx.x == 0) {
        __threadfence();
        unsigned long long t = atomicAdd(&g_barb[b], 1ULL);
        unsigned long long target = (t / NCHUNK + 1ULL) * NCHUNK;
        volatile unsigned long long* p = &g_barb[b];
        while (*p < target) __nanosleep(32);
        __threadfence();
    }
    __syncthreads();
}

__device__ __forceinline__ float dot4(const float4 a, const float4 b)
{
    float r;
    r = a.x * b.x;
    r = fmaf(a.y, b.y, r);
    r = fmaf(a.z, b.z, r);
    r = fmaf(a.w, b.w, r);
    return r;
}

__device__ __forceinline__ void l2_prefetch(const void* p)
{
    asm volatile("prefetch.global.L2 [%0];" :: "l"(p));
}

// ---------------- fused kernel ----------------
// grid = B*NCHUNK = 256 blocks, block = 256 (8 warps), 2 blocks/SM.
__global__ void __launch_bounds__(256, 2) fused_attn(
    const float* __restrict__ query,
    const float* __restrict__ value,
    const int*   __restrict__ mask,
    const float* __restrict__ W_align,
    const float* __restrict__ b_align,
    const float* __restrict__ W_query,
    const float* __restrict__ b_query,
    const float* __restrict__ W_value,
    const float* __restrict__ b_value,
    float* __restrict__ out,
    int L)
{
    const int bid  = blockIdx.x;
    const int b    = bid >> 4;
    const int seg  = bid & 15;
    const int tid  = threadIdx.x;
    const int warp = tid >> 5;
    const int lane = tid & 31;

    __shared__ float s_vec[D];             // query row (ph1) / combined ctx (ph3)
    __shared__ float s_q[D];
    __shared__ int   s_idx[512];
    __shared__ int   s_pop[16], s_off[16], s_tot;
    __shared__ float sm_m[8], sm_s[8];
    __shared__ float sm_ctx[8][D];
    __shared__ float s_e[NCHUNK];
    __shared__ float s_Sinv;

    // ================= Phase 1: q = query @ W_align^T + b_align ===========
    for (int i = tid; i < D; i += 256) s_vec[i] = query[(size_t)b * D + i];
    __syncthreads();
    {
        const int d0 = seg * 32 + warp * 4;
        const float4* x4 = reinterpret_cast<const float4*>(s_vec);
        float4 x[4];
#pragma unroll
        for (int k = 0; k < 4; k++) x[k] = x4[lane + 32 * k];

        float acc[4] = {0.f, 0.f, 0.f, 0.f};
#pragma unroll
        for (int i = 0; i < 4; i++) {
            const float4* wrow = reinterpret_cast<const float4*>(W_align + (size_t)(d0 + i) * D);
#pragma unroll
            for (int k = 0; k < 4; k++) {
                float4 w = wrow[lane + 32 * k];
                acc[i] = fmaf(w.x, x[k].x, acc[i]); acc[i] = fmaf(w.y, x[k].y, acc[i]);
                acc[i] = fmaf(w.z, x[k].z, acc[i]); acc[i] = fmaf(w.w, x[k].w, acc[i]);
            }
        }
#pragma unroll
        for (int o = 16; o > 0; o >>= 1) {
#pragma unroll
            for (int i = 0; i < 4; i++) acc[i] += __shfl_xor_sync(0xffffffffu, acc[i], o);
        }
        if (lane < 4)
            g_q[(size_t)b * D + d0 + lane] = acc[lane] + b_align[d0 + lane];
    }

    // ---- warm L2 with this block's phase-3 W rows (hidden under ph1) ----
    {
        // 32 rows x 2 matrices x 16 sectors (128B) = 1024 touches, 4/thread
        const int dbase = seg * 32;
#pragma unroll
        for (int i = 0; i < 4; i++) {
            const int t   = tid + 256 * i;
            const int mat = t >> 9;             // 0: W_value, 1: W_query
            const int r   = (t >> 4) & 31;      // row within segment
            const int sec = t & 15;             // 128B sector
            const float* p = (mat ? W_query : W_value)
                             + (size_t)(dbase + r) * D + sec * 32;
            l2_prefetch(p);
        }
    }

    batch_barrier(b);   // q[b] visible to this batch's 16 blocks

    // ================= Phase 2: online-softmax over value ==================
    {
        const int RC = L / NCHUNK;          // 512
        const int l0 = seg * RC;

        // ---- compact unmasked row indices ----
        const int* mrow = mask + (size_t)b * L + l0;
        unsigned a0 = __ballot_sync(0xffffffffu, mrow[tid]       == 0);
        unsigned a1 = __ballot_sync(0xffffffffu, mrow[tid + 256] == 0);
        if (lane == 0) { s_pop[warp] = __popc(a0); s_pop[warp + 8] = __popc(a1); }
        __syncthreads();
        if (tid == 0) {
            int acc = 0;
#pragma unroll
            for (int i = 0; i < 16; i++) { s_off[i] = acc; acc += s_pop[i]; }
            s_tot = acc;
        }
        __syncthreads();
        if ((a0 >> lane) & 1)
            s_idx[s_off[warp]     + __popc(a0 & ((1u << lane) - 1))] = warp * 32 + lane;
        if ((a1 >> lane) & 1)
            s_idx[s_off[warp + 8] + __popc(a1 & ((1u << lane) - 1))] = 256 + warp * 32 + lane;
        __syncthreads();
        const int T = s_tot;

        const float4* q4 = reinterpret_cast<const float4*>(g_q + b * D);
        float4 q[4];
#pragma unroll
        for (int k = 0; k < 4; k++) q[k] = q4[lane + 32 * k];

        float m = NEG_INF, s = 0.f;
        float4 ctx[4];
#pragma unroll
        for (int k = 0; k < 4; k++) ctx[k] = make_float4(0.f, 0.f, 0.f, 0.f);

        const float* vbase = value + ((size_t)b * L + l0) * D;

        for (int t0 = warp * 4; t0 < T; t0 += 32) {
            const int n = min(4, T - t0);
            const int j0 = s_idx[t0];
            const int j1 = s_idx[t0 + (n > 1 ? 1 : 0)];
            const int j2 = s_idx[t0 + (n > 2 ? 2 : 0)];
            const int j3 = s_idx[t0 + (n > 3 ? 3 : 0)];

            const float4* p0 = reinterpret_cast<const float4*>(vbase + (size_t)j0 * D);
            const float4* p1 = reinterpret_cast<const float4*>(vbase + (size_t)j1 * D);
            const float4* p2 = reinterpret_cast<const float4*>(vbase + (size_t)j2 * D);
            const float4* p3 = reinterpret_cast<const float4*>(vbase + (size_t)j3 * D);

            float4 v0[4], v1[4], v2[4], v3[4];
#pragma unroll
            for (int k = 0; k < 4; k++) v0[k] = __ldcs(p0 + lane + 32 * k);
#pragma unroll
            for (int k = 0; k < 4; k++) v1[k] = __ldcs(p1 + lane + 32 * k);
#pragma unroll
            for (int k = 0; k < 4; k++) v2[k] = __ldcs(p2 + lane + 32 * k);
#pragma unroll
            for (int k = 0; k < 4; k++) v3[k] = __ldcs(p3 + lane + 32 * k);

            float s0 = 0.f, s1 = 0.f, s2 = 0.f, s3 = 0.f;
#pragma unroll
            for (int k = 0; k < 4; k++) {
                s0 += dot4(v0[k], q[k]);
                s1 += dot4(v1[k], q[k]);
                s2 += dot4(v2[k], q[k]);
                s3 += dot4(v3[k], q[k]);
            }
#pragma unroll
            for (int o = 16; o > 0; o >>= 1) {
                s0 += __shfl_xor_sync(0xffffffffu, s0, o);
                s1 += __shfl_xor_sync(0xffffffffu, s1, o);
                s2 += __shfl_xor_sync(0xffffffffu, s2, o);
                s3 += __shfl_xor_sync(0xffffffffu, s3, o);
            }
            if (n < 2) s1 = NEG_INF;
            if (n < 3) s2 = NEG_INF;
            if (n < 4) s3 = NEG_INF;

            const float m_new = fmaxf(fmaxf(m, fmaxf(s0, s1)), fmaxf(s2, s3));
            const float corr = __expf(m  - m_new);
            const float w0   = __expf(s0 - m_new);
            const float w1   = __expf(s1 - m_new);
            const float w2   = __expf(s2 - m_new);
            const float w3   = __expf(s3 - m_new);
            s = s * corr + w0 + w1 + w2 + w3;
#pragma unroll
            for (int k = 0; k < 4; k++) {
                ctx[k].x = ctx[k].x * corr + fmaf(w1, v1[k].x, w0 * v0[k].x)
                                           + fmaf(w3, v3[k].x, w2 * v2[k].x);
                ctx[k].y = ctx[k].y * corr + fmaf(w1, v1[k].y, w0 * v0[k].y)
                                           + fmaf(w3, v3[k].y, w2 * v2[k].y);
                ctx[k].z = ctx[k].z * corr + fmaf(w1, v1[k].z, w0 * v0[k].z)
                                           + fmaf(w3, v3[k].z, w2 * v2[k].z);
                ctx[k].w = ctx[k].w * corr + fmaf(w1, v1[k].w, w0 * v0[k].w)
                                           + fmaf(w3, v3[k].w, w2 * v2[k].w);
            }
            m = m_new;
        }

        // ---- merge the 8 warps' partials ----
        if (lane == 0) { sm_m[warp] = m; sm_s[warp] = s; }
#pragma unroll
        for (int k = 0; k < 4; k++) {
            const int i = (lane + 32 * k) * 4;
            sm_ctx[warp][i + 0] = ctx[k].x;
            sm_ctx[warp][i + 1] = ctx[k].y;
            sm_ctx[warp][i + 2] = ctx[k].z;
            sm_ctx[warp][i + 3] = ctx[k].w;
        }
        __syncthreads();

        float M = NEG_INF;
#pragma unroll
        for (int wi = 0; wi < 8; wi++) M = fmaxf(M, sm_m[wi]);
        float e[8];
#pragma unroll
        for (int wi = 0; wi < 8; wi++) e[wi] = __expf(sm_m[wi] - M);

        float o0 = 0.f, o1 = 0.f;
#pragma unroll
        for (int wi = 0; wi < 8; wi++) {
            o0 = fmaf(sm_ctx[wi][tid],       e[wi], o0);
            o1 = fmaf(sm_ctx[wi][tid + 256], e[wi], o1);
        }
        g_pctx[(size_t)bid * D + tid]       = o0;
        g_pctx[(size_t)bid * D + tid + 256] = o1;

        if (tid == 0) {
            float S = 0.f;
#pragma unroll
            for (int wi = 0; wi < 8; wi++) S = fmaf(sm_s[wi], e[wi], S);
            g_pm[bid] = M;
            g_ps[bid] = S;
        }
    }

    batch_barrier(b);   // this batch's partials visible

    // ================= Phase 3: combine + dual GEMV + tanh =================
    {
        if (warp == 0) {
            float mv = (lane < NCHUNK) ? g_pm[b * NCHUNK + lane] : NEG_INF;
            float M = mv;
#pragma unroll
            for (int o = 16; o > 0; o >>= 1) M = fmaxf(M, __shfl_xor_sync(0xffffffffu, M, o));
            float e  = (lane < NCHUNK) ? __expf(mv - M) : 0.f;
            float Sp = (lane < NCHUNK) ? g_ps[b * NCHUNK + lane] * e : 0.f;
#pragma unroll
            for (int o = 16; o > 0; o >>= 1) Sp += __shfl_xor_sync(0xffffffffu, Sp, o);
            if (lane < NCHUNK) s_e[lane] = e;
            if (lane == 0) s_Sinv = 1.f / Sp;
        }
        __syncthreads();

        const float Sinv = s_Sinv;
#pragma unroll
        for (int r = 0; r < 2; r++) {
            const int d = tid + 256 * r;
            const float* pc = g_pctx + (size_t)b * NCHUNK * D + d;
            float acc = 0.f;
#pragma unroll
            for (int c = 0; c < NCHUNK; c++)
                acc = fmaf(pc[(size_t)c * D], s_e[c], acc);
            s_vec[d] = acc * Sinv;
            s_q[d]   = g_q[(size_t)b * D + d];
        }
        __syncthreads();

        const int d0 = seg * 32 + warp * 4;
        const float4* c4 = reinterpret_cast<const float4*>(s_vec);
        const float4* q4 = reinterpret_cast<const float4*>(s_q);
        float4 cx[4], qx[4];
#pragma unroll
        for (int k = 0; k < 4; k++) { cx[k] = c4[lane + 32 * k]; qx[k] = q4[lane + 32 * k]; }

        float acc[4] = {0.f, 0.f, 0.f, 0.f};
#pragma unroll
        for (int i = 0; i < 4; i++) {
            const float4* wv = reinterpret_cast<const float4*>(W_value + (size_t)(d0 + i) * D);
            const float4* wq = reinterpret_cast<const float4*>(W_query + (size_t)(d0 + i) * D);
#pragma unroll
            for (int k = 0; k < 4; k++) {
                float4 a = wv[lane + 32 * k];
                float4 g = wq[lane + 32 * k];
                acc[i] += dot4(a, cx[k]);
                acc[i] += dot4(g, qx[k]);
            }
        }
#pragma unroll
        for (int o = 16; o > 0; o >>= 1) {
#pragma unroll
            for (int i = 0; i < 4; i++) acc[i] += __shfl_xor_sync(0xffffffffu, acc[i], o);
        }
        if (lane < 4) {
            const int d = d0 + lane;
            out[(size_t)b * D + d] = tanhf(acc[lane] + b_value[d] + b_query[d]);
        }
    }
}

// ---------------- launch ----------------
extern "C" void kernel_launch(void* const* d_in, const int* in_sizes, int n_in,
                              void* d_out, int out_size)
{
    const float* query   = (const float*)d_in[0];
    const float* value   = (const float*)d_in[1];
    const int*   mask    = (const int*)  d_in[2];
    const float* W_align = (const float*)d_in[3];
    const float* b_align = (const float*)d_in[4];
    const float* W_query = (const float*)d_in[5];
    const float* b_query = (const float*)d_in[6];
    const float* W_value = (const float*)d_in[7];
    const float* b_value = (const float*)d_in[8];
    float* out = (float*)d_out;

    const int B = in_sizes[0] / D;          // 16
    const int L = in_sizes[2] / B;          // 8192

    fused_attn<<<B * NCHUNK, 256>>>(query, value, mask,
                                    W_align, b_align, W_query, b_query,
                                    W_value, b_value, out, L);
}